// round 6
// baseline (speedup 1.0000x reference)
#include <cuda_runtime.h>
#include <cstdint>
#include <cstddef>

#define B_BATCH 1024
#define T_STEPS 100
#define N_IN    784
#define N_HID   100
#define N_OUT   10
#define M_TOT   (B_BATCH * T_STEPS)   // 102400

#define NKS   98          // 784 / 8 k-steps
#define NMT   7           // 112 padded output rows / 16

// Scratch
__device__ float g_YT [(size_t)N_HID * M_TOT];   // Y^T  [100][102400]
__device__ float g_SPT[(size_t)N_HID * M_TOT];   // SP^T [100][102400]
__device__ float g_H2T[(size_t)N_OUT * M_TOT];   // H2^T [10][102400]
// Packed tf32 A-fragments of W1: [NKS][NMT][32 lanes] float4, +32 pad (lookahead)
__device__ float4 g_ApkHi[NKS * NMT * 32 + 32];
__device__ float4 g_ApkLo[NKS * NMT * 32 + 32];

// ---------------- tf32 helpers ----------------
static __device__ __forceinline__ uint32_t f2tf32(float x) {
    uint32_t r;
    asm("cvt.rna.tf32.f32 %0, %1;" : "=r"(r) : "f"(x));
    return r;
}
static __device__ __forceinline__ void split_tf32(float x, uint32_t& hi, uint32_t& lo) {
    hi = f2tf32(x);
    lo = f2tf32(x - __uint_as_float(hi));
}
static __device__ __forceinline__ void mma_tf32(
    float& d0, float& d1, float& d2, float& d3,
    uint32_t a0, uint32_t a1, uint32_t a2, uint32_t a3,
    uint32_t b0, uint32_t b1)
{
    asm volatile(
        "mma.sync.aligned.m16n8k8.row.col.f32.tf32.tf32.f32 "
        "{%0,%1,%2,%3}, {%4,%5,%6,%7}, {%8,%9}, {%0,%1,%2,%3};\n"
        : "+f"(d0), "+f"(d1), "+f"(d2), "+f"(d3)
        : "r"(a0), "r"(a1), "r"(a2), "r"(a3), "r"(b0), "r"(b1));
}

// ---------------- cp.async helpers ----------------
static __device__ __forceinline__ uint32_t smem_u32(const void* p) {
    uint32_t a;
    asm("{ .reg .u64 t; cvta.to.shared.u64 t, %1; cvt.u32.u64 %0, t; }"
        : "=r"(a) : "l"(p));
    return a;
}
static __device__ __forceinline__ void cp_async16(uint32_t dst, const void* src) {
    asm volatile("cp.async.ca.shared.global [%0], [%1], 16;"
                 :: "r"(dst), "l"(src) : "memory");
}
static __device__ __forceinline__ void cp_commit() {
    asm volatile("cp.async.commit_group;" ::: "memory");
}
static __device__ __forceinline__ void cp_wait1() {
    asm volatile("cp.async.wait_group 1;" ::: "memory");
}
static __device__ __forceinline__ void cp_wait0() {
    asm volatile("cp.async.wait_group 0;" ::: "memory");
}

// ============ Prep: pack W1 into tf32 A-fragments (hi/lo) ============
__global__ __launch_bounds__(256) void prep_a_kernel(const float* __restrict__ W1)
{
    const int gid = blockIdx.x * 256 + threadIdx.x;
    if (gid >= NKS * NMT * 32) return;
    const int lane = gid & 31;
    const int mt   = (gid >> 5) % NMT;
    const int s    = (gid >> 5) / NMT;
    const int q = lane >> 2, r = lane & 3;
    const int n0 = mt * 16 + q;
    const int n1 = n0 + 8;
    const int k0 = s * 8 + r;

    const float v0 = (n0 < N_HID) ? W1[(size_t)n0 * N_IN + k0]     : 0.f;
    const float v1 = (n1 < N_HID) ? W1[(size_t)n1 * N_IN + k0]     : 0.f;
    const float v2 = (n0 < N_HID) ? W1[(size_t)n0 * N_IN + k0 + 4] : 0.f;
    const float v3 = (n1 < N_HID) ? W1[(size_t)n1 * N_IN + k0 + 4] : 0.f;

    uint32_t h0, l0, h1, l1, h2, l2, h3, l3;
    split_tf32(v0, h0, l0); split_tf32(v1, h1, l1);
    split_tf32(v2, h2, l2); split_tf32(v3, h3, l3);

    float4 fh, fl;
    fh.x = __uint_as_float(h0); fh.y = __uint_as_float(h1);
    fh.z = __uint_as_float(h2); fh.w = __uint_as_float(h3);
    fl.x = __uint_as_float(l0); fl.y = __uint_as_float(l1);
    fl.z = __uint_as_float(l2); fl.w = __uint_as_float(l3);
    g_ApkHi[gid] = fh;
    g_ApkLo[gid] = fl;
}

// ============ GEMM1 (mma.sync): YT[n][m] = sum_k W1[n,k] X[m,k] ============
// CTA: 256 batch rows (8 warps x 32 m). X staged via cp.async double buffer.
#define XSTRD 12   // floats per row in smem (conflict-free fragment reads)

__global__ __launch_bounds__(256, 1) void gemm1_mma_kernel(const float* __restrict__ X)
{
    __shared__ float Xs[2][256 * XSTRD];

    const int tid  = threadIdx.x;
    const int warp = tid >> 5;
    const int lane = tid & 31;
    const int q = lane >> 2, r = lane & 3;
    const int m0  = blockIdx.x * 256;
    const int m0w = m0 + warp * 32;

    float acc[NMT][4][4];
#pragma unroll
    for (int mt = 0; mt < NMT; ++mt)
#pragma unroll
        for (int nt = 0; nt < 4; ++nt)
#pragma unroll
            for (int i = 0; i < 4; ++i) acc[mt][nt][i] = 0.f;

    // X staging: thread t loads row (m0+t), 32B (= 8 floats of kstep s)
    const float* xsrc = X + (size_t)(m0 + tid) * N_IN;
    const uint32_t xs0 = smem_u32(&Xs[0][0]) + (uint32_t)tid * (XSTRD * 4);
    const uint32_t xs1 = smem_u32(&Xs[1][0]) + (uint32_t)tid * (XSTRD * 4);

    // prologue: stage kstep 0 into buffer 0
    cp_async16(xs0,      xsrc);
    cp_async16(xs0 + 16, xsrc + 4);
    cp_commit();

    // A-fragment running pointers with one-mt lookahead
    const float4* __restrict__ pAh = g_ApkHi + lane;
    const float4* __restrict__ pAl = g_ApkLo + lane;
    float4 ah4 = pAh[0];
    float4 al4 = pAl[0];
    int aidx = 32;

    // per-warp smem read offsets for the 4 n-tiles (batch rows)
    int xoff[4];
#pragma unroll
    for (int nt = 0; nt < 4; ++nt)
        xoff[nt] = (warp * 32 + nt * 8 + q) * XSTRD + r;

    for (int s = 0; s < NKS; ++s) {
        const int p = s & 1;
        // stage next kstep into other buffer
        if (s + 1 < NKS) {
            const uint32_t dst = (p ? xs0 : xs1);
            const float* src = xsrc + (s + 1) * 8;
            cp_async16(dst,      src);
            cp_async16(dst + 16, src + 4);
            cp_commit();
            cp_wait1();
        } else {
            cp_wait0();
        }
        __syncthreads();

        const float* xb = &Xs[p][0];

        // B fragments from staged X: conflict-free LDS, split in regs
        uint32_t bh[4][2], bl[4][2];
#pragma unroll
        for (int nt = 0; nt < 4; ++nt) {
            const float x0 = xb[xoff[nt]];
            const float x1 = xb[xoff[nt] + 4];
            split_tf32(x0, bh[nt][0], bl[nt][0]);
            split_tf32(x1, bh[nt][1], bl[nt][1]);
        }

#pragma unroll
        for (int mt = 0; mt < NMT; ++mt) {
            // lookahead: next (s,mt) fragment (layout is flat, pad covers tail)
            const float4 nah = pAh[aidx];
            const float4 nal = pAl[aidx];
            aidx += 32;

            const uint32_t ah[4] = {
                __float_as_uint(ah4.x), __float_as_uint(ah4.y),
                __float_as_uint(ah4.z), __float_as_uint(ah4.w) };
            const uint32_t al[4] = {
                __float_as_uint(al4.x), __float_as_uint(al4.y),
                __float_as_uint(al4.z), __float_as_uint(al4.w) };
#pragma unroll
            for (int nt = 0; nt < 4; ++nt)
                mma_tf32(acc[mt][nt][0], acc[mt][nt][1], acc[mt][nt][2], acc[mt][nt][3],
                         ah[0], ah[1], ah[2], ah[3], bh[nt][0], bh[nt][1]);
#pragma unroll
            for (int nt = 0; nt < 4; ++nt)
                mma_tf32(acc[mt][nt][0], acc[mt][nt][1], acc[mt][nt][2], acc[mt][nt][3],
                         ah[0], ah[1], ah[2], ah[3], bl[nt][0], bl[nt][1]);
#pragma unroll
            for (int nt = 0; nt < 4; ++nt)
                mma_tf32(acc[mt][nt][0], acc[mt][nt][1], acc[mt][nt][2], acc[mt][nt][3],
                         al[0], al[1], al[2], al[3], bh[nt][0], bh[nt][1]);

            ah4 = nah;
            al4 = nal;
        }
        __syncthreads();   // protect buffer p before next-next stage overwrites
    }

    // epilogue -> YT[n][m], float2 stores
#pragma unroll
    for (int mt = 0; mt < NMT; ++mt) {
        const int n0 = mt * 16 + q;
#pragma unroll
        for (int nt = 0; nt < 4; ++nt) {
            const int m = m0w + nt * 8 + 2 * r;
            if (n0 < N_HID)
                *reinterpret_cast<float2*>(g_YT + (size_t)n0 * M_TOT + m) =
                    make_float2(acc[mt][nt][0], acc[mt][nt][1]);
            if (n0 + 8 < N_HID)
                *reinterpret_cast<float2*>(g_YT + (size_t)(n0 + 8) * M_TOT + m) =
                    make_float2(acc[mt][nt][2], acc[mt][nt][3]);
        }
    }
}

// ============ Phase A: layer-1 scan, thread = (h, b), walks t ============
__global__ __launch_bounds__(256) void scan1_kernel(
    const float* __restrict__ w_syn1, const float* __restrict__ b1)
{
    const int gid = blockIdx.x * 256 + threadIdx.x;
    const int h = gid >> 10;
    const int b = gid & 1023;

    const float inv1 = 1.f / (1.f + expf(-w_syn1[0]));
    const float bh = b1[h];

    const float* Yp = g_YT  + (size_t)h * M_TOT + (size_t)b * T_STEPS;
    float*       Sp = g_SPT + (size_t)h * M_TOT + (size_t)b * T_STEPS;

    float hs = 0.f, v = 0.f;
#pragma unroll 1
    for (int i = 0; i < T_STEPS / 4; ++i) {
        const float4 yv = *reinterpret_cast<const float4*>(Yp + i * 4);
        const float ya[4] = {yv.x, yv.y, yv.z, yv.w};
        float sp[4];
#pragma unroll
        for (int j = 0; j < 4; ++j) {
            hs = (hs - hs * inv1) + ya[j];
            const float h1 = hs + bh;
            v = v + (h1 - v) * 0.5f;
            const float s = (v >= 1.0f) ? 1.f : 0.f;
            v = v * (1.f - s);
            sp[j] = s;
        }
        *reinterpret_cast<float4*>(Sp + i * 4) =
            make_float4(sp[0], sp[1], sp[2], sp[3]);
    }
}

// ============ Phase B: H2T[o][m] = sum_h SPT[h][m] * W2[o,h] ============
__global__ __launch_bounds__(256) void gemm2_kernel(const float* __restrict__ W2)
{
    __shared__ float w2t[N_HID * N_OUT];
    const int tid = threadIdx.x;
    for (int i = tid; i < N_HID * N_OUT; i += 256) {
        const int o = i / N_HID, h = i % N_HID;
        w2t[h * N_OUT + o] = W2[i];
    }
    __syncthreads();

    const int m = blockIdx.x * 256 + tid;
    float acc[N_OUT];
#pragma unroll
    for (int o = 0; o < N_OUT; ++o) acc[o] = 0.f;

#pragma unroll 4
    for (int h = 0; h < N_HID; ++h) {
        const float v = g_SPT[(size_t)h * M_TOT + m];
#pragma unroll
        for (int o = 0; o < N_OUT; ++o)
            acc[o] = fmaf(v, w2t[h * N_OUT + o], acc[o]);
    }
#pragma unroll
    for (int o = 0; o < N_OUT; ++o)
        g_H2T[(size_t)o * M_TOT + m] = acc[o];
}

// ============ Phase C: layer-2 scan, thread = (o, b) ============
__global__ __launch_bounds__(256) void scan2_kernel(
    const float* __restrict__ w_syn2, const float* __restrict__ b2,
    float* __restrict__ out)
{
    const int gt = blockIdx.x * 256 + threadIdx.x;
    const int o  = gt >> 10;
    const int b  = gt & 1023;

    const float inv2 = 1.f / (1.f + expf(-w_syn2[0]));
    const float bo = b2[o];
    const float* hp = g_H2T + (size_t)o * M_TOT + (size_t)b * T_STEPS;

    float hs = 0.f, v = 0.f;
#pragma unroll 1
    for (int i = 0; i < T_STEPS / 4; ++i) {
        const float4 pv = *reinterpret_cast<const float4*>(hp + i * 4);
        const float pa[4] = {pv.x, pv.y, pv.z, pv.w};
#pragma unroll
        for (int j = 0; j < 4; ++j) {
            hs = (hs - hs * inv2) + pa[j];
            const float h2 = hs + bo;
            v = v + (h2 - v) * 0.5f;
        }
    }
    out[b * N_OUT + o] = v;
}

// ---------------- entry ----------------
extern "C" void kernel_launch(void* const* d_in, const int* in_sizes, int n_in,
                              void* d_out, int out_size) {
    const float* x   = (const float*)d_in[0];
    const float* w1s = (const float*)d_in[1];
    const float* W1  = (const float*)d_in[2];
    const float* b1  = (const float*)d_in[3];
    const float* w2s = (const float*)d_in[4];
    const float* W2  = (const float*)d_in[5];
    const float* b2  = (const float*)d_in[6];
    float* out = (float*)d_out;

    prep_a_kernel<<<(NKS * NMT * 32 + 255) / 256, 256>>>(W1);
    gemm1_mma_kernel<<<M_TOT / 256, 256>>>(x);
    scan1_kernel<<<M_TOT / 256, 256>>>(w1s, b1);
    gemm2_kernel<<<M_TOT / 256, 256>>>(W2);
    scan2_kernel<<<(B_BATCH * N_OUT) / 256, 256>>>(w2s, b2, out);
}

// round 7
// speedup vs baseline: 1.1223x; 1.1223x over previous
#include <cuda_runtime.h>
#include <cstdint>
#include <cstddef>

#define B_BATCH 1024
#define T_STEPS 100
#define N_IN    784
#define N_HID   100
#define N_OUT   10
#define M_TOT   (B_BATCH * T_STEPS)   // 102400

#define NKS   98          // 784 / 8 k-steps
#define NMT_T 3           // tensor path: cols 0..47 (3 x m16)

// Scratch
__device__ float g_YT [(size_t)N_HID * M_TOT];   // Y^T  [100][102400]
__device__ float g_SPT[(size_t)N_HID * M_TOT];   // SP^T [100][102400]
__device__ float g_H2T[(size_t)N_OUT * M_TOT];   // H2^T [10][102400]
// Packed tf32 A-fragments of W1 (cols 0..47): [NKS][NMT_T][32] float4 (+pad)
__device__ float4 g_ApkHi[NKS * NMT_T * 32 + 32];
__device__ float4 g_ApkLo[NKS * NMT_T * 32 + 32];

// ---------------- tf32 / mma helpers ----------------
static __device__ __forceinline__ uint32_t f2tf32(float x) {
    uint32_t r;
    asm("cvt.rna.tf32.f32 %0, %1;" : "=r"(r) : "f"(x));
    return r;
}
static __device__ __forceinline__ void split_tf32(float x, uint32_t& hi, uint32_t& lo) {
    hi = f2tf32(x);
    lo = f2tf32(x - __uint_as_float(hi));
}
static __device__ __forceinline__ void mma_tf32(
    float& d0, float& d1, float& d2, float& d3,
    uint32_t a0, uint32_t a1, uint32_t a2, uint32_t a3,
    uint32_t b0, uint32_t b1)
{
    asm volatile(
        "mma.sync.aligned.m16n8k8.row.col.f32.tf32.tf32.f32 "
        "{%0,%1,%2,%3}, {%4,%5,%6,%7}, {%8,%9}, {%0,%1,%2,%3};\n"
        : "+f"(d0), "+f"(d1), "+f"(d2), "+f"(d3)
        : "r"(a0), "r"(a1), "r"(a2), "r"(a3), "r"(b0), "r"(b1));
}

// ---------------- fp32x2 helpers ----------------
static __device__ __forceinline__ unsigned long long lds_u64(uint32_t addr) {
    unsigned long long v;
    asm volatile("ld.shared.b64 %0, [%1];" : "=l"(v) : "r"(addr));
    return v;
}
static __device__ __forceinline__ unsigned long long fma2(
    unsigned long long a, unsigned long long b, unsigned long long c) {
    unsigned long long d;
    asm("fma.rn.f32x2 %0, %1, %2, %3;" : "=l"(d) : "l"(a), "l"(b), "l"(c));
    return d;
}
static __device__ __forceinline__ uint32_t smem_u32(const void* p) {
    uint32_t a;
    asm("{ .reg .u64 t; cvta.to.shared.u64 t, %1; cvt.u32.u64 %0, t; }"
        : "=r"(a) : "l"(p));
    return a;
}

// ============ Prep: pack W1 cols 0..47 into tf32 A-fragments ============
__global__ __launch_bounds__(256) void prep_a_kernel(const float* __restrict__ W1)
{
    const int gid = blockIdx.x * 256 + threadIdx.x;
    if (gid >= NKS * NMT_T * 32) return;
    const int lane = gid & 31;
    const int mt   = (gid >> 5) % NMT_T;
    const int s    = (gid >> 5) / NMT_T;
    const int q = lane >> 2, r = lane & 3;
    const int n0 = mt * 16 + q;       // < 48
    const int n1 = n0 + 8;
    const int k0 = s * 8 + r;

    const float v0 = W1[(size_t)n0 * N_IN + k0];
    const float v1 = W1[(size_t)n1 * N_IN + k0];
    const float v2 = W1[(size_t)n0 * N_IN + k0 + 4];
    const float v3 = W1[(size_t)n1 * N_IN + k0 + 4];

    uint32_t h0, l0, h1, l1, h2, l2, h3, l3;
    split_tf32(v0, h0, l0); split_tf32(v1, h1, l1);
    split_tf32(v2, h2, l2); split_tf32(v3, h3, l3);

    float4 fh, fl;
    fh.x = __uint_as_float(h0); fh.y = __uint_as_float(h1);
    fh.z = __uint_as_float(h2); fh.w = __uint_as_float(h3);
    fl.x = __uint_as_float(l0); fl.y = __uint_as_float(l1);
    fl.z = __uint_as_float(l2); fl.w = __uint_as_float(l3);
    g_ApkHi[gid] = fh;
    g_ApkLo[gid] = fl;
}

// ==================== fused GEMM1: two CTA flavors ====================
// tensor CTA (blockIdx%3==0): cols 0..47 via mma.sync (R5 structure, NMT_T=3)
// fp32  CTA (else):           cols 48..99 via FFMA2 (R3 structure, 28 pairs)

#define BKg  16
#define XSTR 133   // float2 per k-row (X tile, 128 rows + pad)
#define WSTR 29    // float2 per k-row (28 pairs + pad)

static __device__ __forceinline__ void tensor_block(
    int tb, const float* __restrict__ X)
{
    const int tid  = threadIdx.x;
    const int warp = tid >> 5;
    const int lane = tid & 31;
    const int q = lane >> 2, r = lane & 3;
    const int m0w = tb * 256 + warp * 32;

    float acc[NMT_T][4][4];
#pragma unroll
    for (int mt = 0; mt < NMT_T; ++mt)
#pragma unroll
        for (int nt = 0; nt < 4; ++nt)
#pragma unroll
            for (int i = 0; i < 4; ++i) acc[mt][nt][i] = 0.f;

    const float* xr[4];
#pragma unroll
    for (int nt = 0; nt < 4; ++nt)
        xr[nt] = X + (size_t)(m0w + nt * 8 + q) * N_IN + r;

    const float4* __restrict__ Ah = g_ApkHi;
    const float4* __restrict__ Al = g_ApkLo;

    for (int s = 0; s < NKS; ++s) {
        uint32_t bh[4][2], bl[4][2];
#pragma unroll
        for (int nt = 0; nt < 4; ++nt) {
            const float x0 = xr[nt][s * 8];
            const float x1 = xr[nt][s * 8 + 4];
            split_tf32(x0, bh[nt][0], bl[nt][0]);
            split_tf32(x1, bh[nt][1], bl[nt][1]);
        }

#pragma unroll
        for (int mt = 0; mt < NMT_T; ++mt) {
            const float4 ah4 = Ah[(s * NMT_T + mt) * 32 + lane];
            const float4 al4 = Al[(s * NMT_T + mt) * 32 + lane];
            const uint32_t ah[4] = {
                __float_as_uint(ah4.x), __float_as_uint(ah4.y),
                __float_as_uint(ah4.z), __float_as_uint(ah4.w) };
            const uint32_t al[4] = {
                __float_as_uint(al4.x), __float_as_uint(al4.y),
                __float_as_uint(al4.z), __float_as_uint(al4.w) };
#pragma unroll
            for (int nt = 0; nt < 4; ++nt)
                mma_tf32(acc[mt][nt][0], acc[mt][nt][1], acc[mt][nt][2], acc[mt][nt][3],
                         ah[0], ah[1], ah[2], ah[3], bh[nt][0], bh[nt][1]);
#pragma unroll
            for (int nt = 0; nt < 4; ++nt)
                mma_tf32(acc[mt][nt][0], acc[mt][nt][1], acc[mt][nt][2], acc[mt][nt][3],
                         ah[0], ah[1], ah[2], ah[3], bl[nt][0], bl[nt][1]);
#pragma unroll
            for (int nt = 0; nt < 4; ++nt)
                mma_tf32(acc[mt][nt][0], acc[mt][nt][1], acc[mt][nt][2], acc[mt][nt][3],
                         al[0], al[1], al[2], al[3], bh[nt][0], bh[nt][1]);
        }
    }

#pragma unroll
    for (int mt = 0; mt < NMT_T; ++mt) {
        const int n0 = mt * 16 + q;     // < 48, always valid
#pragma unroll
        for (int nt = 0; nt < 4; ++nt) {
            const int m = m0w + nt * 8 + 2 * r;
            *reinterpret_cast<float2*>(g_YT + (size_t)n0 * M_TOT + m) =
                make_float2(acc[mt][nt][0], acc[mt][nt][1]);
            *reinterpret_cast<float2*>(g_YT + (size_t)(n0 + 8) * M_TOT + m) =
                make_float2(acc[mt][nt][2], acc[mt][nt][3]);
        }
    }
}

static __device__ __forceinline__ void fp32_block(
    int fb, const float* __restrict__ X, const float* __restrict__ W1,
    float2* Xs, float2* Ws)
{
    const int tid = threadIdx.x;           // 0..255
    const bool active = (tid < 224);       // 7 x 32 compute threads
    const int x = tid % 7;                 // pair group
    const int y = tid / 7;                 // m group (0..31 for active)
    const int m0 = fb * 128;

    unsigned long long acc[4][4];          // [r: m rows][j: pairs]
#pragma unroll
    for (int r = 0; r < 4; ++r)
#pragma unroll
        for (int j = 0; j < 4; ++j) acc[r][j] = 0ull;

    // X loader: 128 rows x 4 slots = 512 units, two passes (256 threads)
    const int xr1 = tid >> 2, xs1 = tid & 3;
    const int xu2 = tid + 256;
    const int xr2 = xu2 >> 2, xs2 = xu2 & 3;
    // W loader: 56 rows (48..103) x 4 slots = 224 units, one pass
    const bool pw = (tid < 224);
    const int wu = tid;
    const int widx = wu >> 2;               // 0..55
    const int wslot = wu & 3;
    const int wrow = 48 + widx;              // 48..103
    const bool wvalid = (wrow < N_HID);

    const float4* X4 = reinterpret_cast<const float4*>(X);
    const float4* W4 = reinterpret_cast<const float4*>(W1);
    const size_t xoff1 = (size_t)(m0 + xr1) * (N_IN / 4) + xs1;
    const size_t xoff2 = (size_t)(m0 + xr2) * (N_IN / 4) + xs2;
    const size_t woff  = (size_t)(wvalid ? wrow : 0) * (N_IN / 4) + wslot;

    const uint32_t xs_base = smem_u32(Xs);
    const uint32_t ws_base = smem_u32(Ws);

    for (int kc = 0; kc < N_IN / BKg; ++kc) {   // 49 chunks of 16 k
        float4 xa = X4[xoff1 + (size_t)kc * 4];
        float4 xb = X4[xoff2 + (size_t)kc * 4];
        float4 wv = make_float4(0.f, 0.f, 0.f, 0.f);
        if (pw && wvalid) wv = W4[woff + (size_t)kc * 4];

        __syncthreads();

        {
            float v[4] = {xa.x, xa.y, xa.z, xa.w};
#pragma unroll
            for (int j = 0; j < 4; ++j)
                Xs[(xs1 * 4 + j) * XSTR + xr1] = make_float2(v[j], v[j]);
        }
        {
            float v[4] = {xb.x, xb.y, xb.z, xb.w};
#pragma unroll
            for (int j = 0; j < 4; ++j)
                Xs[(xs2 * 4 + j) * XSTR + xr2] = make_float2(v[j], v[j]);
        }
        if (pw) {
            float v[4] = {wv.x, wv.y, wv.z, wv.w};
            const int q    = (widx < 28) ? widx : widx - 28;
            const int half = (widx < 28) ? 0 : 1;
#pragma unroll
            for (int j = 0; j < 4; ++j)
                reinterpret_cast<float*>(&Ws[(wslot * 4 + j) * WSTR + q])[half] = v[j];
        }
        __syncthreads();

        if (active) {
#pragma unroll
            for (int k = 0; k < BKg; ++k) {
                const uint32_t xaddr = xs_base + (uint32_t)(k * XSTR + y) * 8u;
                const uint32_t waddr = ws_base + (uint32_t)(k * WSTR + x) * 8u;
                unsigned long long a[4], bb[4];
#pragma unroll
                for (int r = 0; r < 4; ++r)
                    a[r] = lds_u64(xaddr + (uint32_t)(32 * r) * 8u);
#pragma unroll
                for (int j = 0; j < 4; ++j)
                    bb[j] = lds_u64(waddr + (uint32_t)(7 * j) * 8u);
#pragma unroll
                for (int r = 0; r < 4; ++r)
#pragma unroll
                    for (int j = 0; j < 4; ++j)
                        acc[r][j] = fma2(a[r], bb[j], acc[r][j]);
            }
        }
    }

    if (active) {
        // epilogue: pair (48+q, 76+q), q = x + 7j; store to YT (transposed)
#pragma unroll
        for (int r = 0; r < 4; ++r) {
            const int m = m0 + y + 32 * r;
#pragma unroll
            for (int j = 0; j < 4; ++j) {
                const int q = x + 7 * j;
                const float lo = __uint_as_float((uint32_t)(acc[r][j] & 0xffffffffull));
                const float hi = __uint_as_float((uint32_t)(acc[r][j] >> 32));
                g_YT[(size_t)(48 + q) * M_TOT + m] = lo;
                if (76 + q < N_HID)
                    g_YT[(size_t)(76 + q) * M_TOT + m] = hi;
            }
        }
    }
}

__global__ __launch_bounds__(256, 2) void gemm1_fused_kernel(
    const float* __restrict__ X, const float* __restrict__ W1)
{
    __shared__ float2 Xs[BKg * XSTR];
    __shared__ float2 Ws[BKg * WSTR];

    const int b = blockIdx.x;
    if (b % 3 == 0) {
        tensor_block(b / 3, X);
    } else {
        fp32_block(b - b / 3 - 1, X, W1, Xs, Ws);
    }
}

// ============ Phase A: layer-1 scan, thread = (h, b), walks t ============
__global__ __launch_bounds__(256) void scan1_kernel(
    const float* __restrict__ w_syn1, const float* __restrict__ b1)
{
    const int gid = blockIdx.x * 256 + threadIdx.x;
    const int h = gid >> 10;
    const int b = gid & 1023;

    const float inv1 = 1.f / (1.f + expf(-w_syn1[0]));
    const float bh = b1[h];

    const float* Yp = g_YT  + (size_t)h * M_TOT + (size_t)b * T_STEPS;
    float*       Sp = g_SPT + (size_t)h * M_TOT + (size_t)b * T_STEPS;

    float hs = 0.f, v = 0.f;
#pragma unroll 1
    for (int i = 0; i < T_STEPS / 4; ++i) {
        const float4 yv = *reinterpret_cast<const float4*>(Yp + i * 4);
        const float ya[4] = {yv.x, yv.y, yv.z, yv.w};
        float sp[4];
#pragma unroll
        for (int j = 0; j < 4; ++j) {
            hs = (hs - hs * inv1) + ya[j];
            const float h1 = hs + bh;
            v = v + (h1 - v) * 0.5f;
            const float s = (v >= 1.0f) ? 1.f : 0.f;
            v = v * (1.f - s);
            sp[j] = s;
        }
        *reinterpret_cast<float4*>(Sp + i * 4) =
            make_float4(sp[0], sp[1], sp[2], sp[3]);
    }
}

// ============ Phase B: H2T[o][m] = sum_h SPT[h][m] * W2[o,h] ============
__global__ __launch_bounds__(256) void gemm2_kernel(const float* __restrict__ W2)
{
    __shared__ float w2t[N_HID * N_OUT];
    const int tid = threadIdx.x;
    for (int i = tid; i < N_HID * N_OUT; i += 256) {
        const int o = i / N_HID, h = i % N_HID;
        w2t[h * N_OUT + o] = W2[i];
    }
    __syncthreads();

    const int m = blockIdx.x * 256 + tid;
    float acc[N_OUT];
#pragma unroll
    for (int o = 0; o < N_OUT; ++o) acc[o] = 0.f;

#pragma unroll 4
    for (int h = 0; h < N_HID; ++h) {
        const float v = g_SPT[(size_t)h * M_TOT + m];
#pragma unroll
        for (int o = 0; o < N_OUT; ++o)
            acc[o] = fmaf(v, w2t[h * N_OUT + o], acc[o]);
    }
#pragma unroll
    for (int o = 0; o < N_OUT; ++o)
        g_H2T[(size_t)o * M_TOT + m] = acc[o];
}

// ============ Phase C: layer-2 scan, thread = (o, b) ============
__global__ __launch_bounds__(256) void scan2_kernel(
    const float* __restrict__ w_syn2, const float* __restrict__ b2,
    float* __restrict__ out)
{
    const int gt = blockIdx.x * 256 + threadIdx.x;
    const int o  = gt >> 10;
    const int b  = gt & 1023;

    const float inv2 = 1.f / (1.f + expf(-w_syn2[0]));
    const float bo = b2[o];
    const float* hp = g_H2T + (size_t)o * M_TOT + (size_t)b * T_STEPS;

    float hs = 0.f, v = 0.f;
#pragma unroll 1
    for (int i = 0; i < T_STEPS / 4; ++i) {
        const float4 pv = *reinterpret_cast<const float4*>(hp + i * 4);
        const float pa[4] = {pv.x, pv.y, pv.z, pv.w};
#pragma unroll
        for (int j = 0; j < 4; ++j) {
            hs = (hs - hs * inv2) + pa[j];
            const float h2 = hs + bo;
            v = v + (h2 - v) * 0.5f;
        }
    }
    out[b * N_OUT + o] = v;
}

// ---------------- entry ----------------
extern "C" void kernel_launch(void* const* d_in, const int* in_sizes, int n_in,
                              void* d_out, int out_size) {
    const float* x   = (const float*)d_in[0];  // [1024, 100, 784]
    const float* w1s = (const float*)d_in[1];
    const float* W1  = (const float*)d_in[2];  // [100, 784]
    const float* b1  = (const float*)d_in[3];
    const float* w2s = (const float*)d_in[4];
    const float* W2  = (const float*)d_in[5];  // [10, 100]
    const float* b2  = (const float*)d_in[6];
    float* out = (float*)d_out;                // [1024, 10]

    prep_a_kernel<<<(NKS * NMT_T * 32 + 255) / 256, 256>>>(W1);
    // 400 tensor CTAs (256 m each) + 800 fp32 CTAs (128 m each), interleaved
    gemm1_fused_kernel<<<1200, 256>>>(x, W1);
    scan1_kernel<<<M_TOT / 256, 256>>>(w1s, b1);
    gemm2_kernel<<<M_TOT / 256, 256>>>(W2);
    scan2_kernel<<<(B_BATCH * N_OUT) / 256, 256>>>(w2s, b2, out);
}

// round 8
// speedup vs baseline: 1.6390x; 1.4604x over previous
#include <cuda_runtime.h>
#include <cstdint>
#include <cstddef>

#define B_BATCH 1024
#define T_STEPS 100
#define N_IN    784
#define N_HID   100
#define N_OUT   10
#define M_TOT   (B_BATCH * T_STEPS)   // 102400

#define NKS   98          // 784 / 8 k-steps (k8 each)
#define NCH   49          // 784 / 16 chunks (2 ksteps per chunk)

// Scratch
__device__ float g_YT [(size_t)N_HID * M_TOT];   // Y^T  [100][102400]
__device__ float g_SPT[(size_t)N_HID * M_TOT];   // SP^T [100][102400]
__device__ float g_H2T[(size_t)N_OUT * M_TOT];   // H2^T [10][102400]
// Packed tf32 A-fragments of W1, k-permuted, split by column-half:
// half0: mt 0..3 (cols 0..63), half1: mt 4..6 (cols 64..111, pad >=100)
__device__ float4 g_ApkHi0[NKS * 4 * 32 + 32];
__device__ float4 g_ApkLo0[NKS * 4 * 32 + 32];
__device__ float4 g_ApkHi1[NKS * 3 * 32 + 32];
__device__ float4 g_ApkLo1[NKS * 3 * 32 + 32];

// ---------------- tf32 / mma helpers ----------------
static __device__ __forceinline__ uint32_t f2tf32(float x) {
    uint32_t r;
    asm("cvt.rna.tf32.f32 %0, %1;" : "=r"(r) : "f"(x));
    return r;
}
static __device__ __forceinline__ void split_tf32(float x, uint32_t& hi, uint32_t& lo) {
    hi = f2tf32(x);
    lo = f2tf32(x - __uint_as_float(hi));
}
static __device__ __forceinline__ void mma_tf32(
    float& d0, float& d1, float& d2, float& d3,
    uint32_t a0, uint32_t a1, uint32_t a2, uint32_t a3,
    uint32_t b0, uint32_t b1)
{
    asm volatile(
        "mma.sync.aligned.m16n8k8.row.col.f32.tf32.tf32.f32 "
        "{%0,%1,%2,%3}, {%4,%5,%6,%7}, {%8,%9}, {%0,%1,%2,%3};\n"
        : "+f"(d0), "+f"(d1), "+f"(d2), "+f"(d3)
        : "r"(a0), "r"(a1), "r"(a2), "r"(a3), "r"(b0), "r"(b1));
}

// ============ Prep: pack W1 into k-PERMUTED tf32 A-fragments ============
// kstep s2 = 2c+ph covers cols {16c+4r+2ph, 16c+4r+2ph+1} at positions (r, r+4).
__global__ __launch_bounds__(256) void prep_a_kernel(const float* __restrict__ W1)
{
    const int gid = blockIdx.x * 256 + threadIdx.x;
    if (gid >= NKS * 7 * 32) return;
    const int lane = gid & 31;
    const int mt   = (gid >> 5) % 7;
    const int s2   = (gid >> 5) / 7;
    const int q = lane >> 2, r = lane & 3;
    const int c  = s2 >> 1, ph = s2 & 1;

    const int kA = 16 * c + 4 * r + 2 * ph;   // fragment position r
    const int kB = kA + 1;                    // fragment position r+4
    const int n0 = mt * 16 + q;
    const int n1 = n0 + 8;

    const float v0 = (n0 < N_HID) ? W1[(size_t)n0 * N_IN + kA] : 0.f;
    const float v1 = (n1 < N_HID) ? W1[(size_t)n1 * N_IN + kA] : 0.f;
    const float v2 = (n0 < N_HID) ? W1[(size_t)n0 * N_IN + kB] : 0.f;
    const float v3 = (n1 < N_HID) ? W1[(size_t)n1 * N_IN + kB] : 0.f;

    uint32_t h0, l0, h1, l1, h2, l2, h3, l3;
    split_tf32(v0, h0, l0); split_tf32(v1, h1, l1);
    split_tf32(v2, h2, l2); split_tf32(v3, h3, l3);

    float4 fh, fl;
    fh.x = __uint_as_float(h0); fh.y = __uint_as_float(h1);
    fh.z = __uint_as_float(h2); fh.w = __uint_as_float(h3);
    fl.x = __uint_as_float(l0); fl.y = __uint_as_float(l1);
    fl.z = __uint_as_float(l2); fl.w = __uint_as_float(l3);

    if (mt < 4) {
        const int idx = (s2 * 4 + mt) * 32 + lane;
        g_ApkHi0[idx] = fh;
        g_ApkLo0[idx] = fl;
    } else {
        const int idx = (s2 * 3 + (mt - 4)) * 32 + lane;
        g_ApkHi1[idx] = fh;
        g_ApkLo1[idx] = fl;
    }
}

// ============ GEMM1: YT[n][m] = sum_k W1[n,k] X[m,k] (tf32x3) ============
// grid (400, 2): x = 256-row m-block, y = column half. 256 thr, 2 CTA/SM.
template <int NMTY, int MTBASE>
static __device__ __forceinline__ void gemm_half(
    const float* __restrict__ X,
    const float4* __restrict__ Ah, const float4* __restrict__ Al)
{
    const int tid  = threadIdx.x;
    const int warp = tid >> 5;
    const int lane = tid & 31;
    const int q = lane >> 2, r = lane & 3;
    const int m0w = blockIdx.x * 256 + warp * 32;

    float acc[NMTY][4][4];
#pragma unroll
    for (int mt = 0; mt < NMTY; ++mt)
#pragma unroll
        for (int nt = 0; nt < 4; ++nt)
#pragma unroll
            for (int i = 0; i < 4; ++i) acc[mt][nt][i] = 0.f;

    // float4 X pointers: lane reads X[m][16c+4r .. +3] per 16-col chunk
    const float4* xr[4];
#pragma unroll
    for (int nt = 0; nt < 4; ++nt)
        xr[nt] = reinterpret_cast<const float4*>(X)
               + (size_t)(m0w + nt * 8 + q) * (N_IN / 4) + r;

    // rolling A-fragment lookahead (uniform stride within this half)
    int aidx = lane;
    float4 ah4 = Ah[aidx];
    float4 al4 = Al[aidx];
    aidx += 32;

    for (int c = 0; c < NCH; ++c) {
        float4 V[4];
#pragma unroll
        for (int nt = 0; nt < 4; ++nt) V[nt] = xr[nt][(size_t)c * 4];

#pragma unroll
        for (int ph = 0; ph < 2; ++ph) {
            uint32_t bh[4][2], bl[4][2];
#pragma unroll
            for (int nt = 0; nt < 4; ++nt) {
                const float x0 = ph ? V[nt].z : V[nt].x;
                const float x1 = ph ? V[nt].w : V[nt].y;
                split_tf32(x0, bh[nt][0], bl[nt][0]);
                split_tf32(x1, bh[nt][1], bl[nt][1]);
            }

#pragma unroll
            for (int mt = 0; mt < NMTY; ++mt) {
                const float4 nah = Ah[aidx];
                const float4 nal = Al[aidx];
                aidx += 32;

                const uint32_t ah[4] = {
                    __float_as_uint(ah4.x), __float_as_uint(ah4.y),
                    __float_as_uint(ah4.z), __float_as_uint(ah4.w) };
                const uint32_t al[4] = {
                    __float_as_uint(al4.x), __float_as_uint(al4.y),
                    __float_as_uint(al4.z), __float_as_uint(al4.w) };
#pragma unroll
                for (int nt = 0; nt < 4; ++nt)
                    mma_tf32(acc[mt][nt][0], acc[mt][nt][1],
                             acc[mt][nt][2], acc[mt][nt][3],
                             ah[0], ah[1], ah[2], ah[3], bh[nt][0], bh[nt][1]);
#pragma unroll
                for (int nt = 0; nt < 4; ++nt)
                    mma_tf32(acc[mt][nt][0], acc[mt][nt][1],
                             acc[mt][nt][2], acc[mt][nt][3],
                             ah[0], ah[1], ah[2], ah[3], bl[nt][0], bl[nt][1]);
#pragma unroll
                for (int nt = 0; nt < 4; ++nt)
                    mma_tf32(acc[mt][nt][0], acc[mt][nt][1],
                             acc[mt][nt][2], acc[mt][nt][3],
                             al[0], al[1], al[2], al[3], bh[nt][0], bh[nt][1]);

                ah4 = nah;
                al4 = nal;
            }
        }
    }

    // epilogue -> YT[n][m]
#pragma unroll
    for (int mt = 0; mt < NMTY; ++mt) {
        const int n0 = (MTBASE + mt) * 16 + q;
#pragma unroll
        for (int nt = 0; nt < 4; ++nt) {
            const int m = m0w + nt * 8 + 2 * r;
            if (n0 < N_HID)
                *reinterpret_cast<float2*>(g_YT + (size_t)n0 * M_TOT + m) =
                    make_float2(acc[mt][nt][0], acc[mt][nt][1]);
            if (n0 + 8 < N_HID)
                *reinterpret_cast<float2*>(g_YT + (size_t)(n0 + 8) * M_TOT + m) =
                    make_float2(acc[mt][nt][2], acc[mt][nt][3]);
        }
    }
}

__global__ __launch_bounds__(256, 2) void gemm1_mma_kernel(const float* __restrict__ X)
{
    if (blockIdx.y == 0)
        gemm_half<4, 0>(X, g_ApkHi0, g_ApkLo0);
    else
        gemm_half<3, 4>(X, g_ApkHi1, g_ApkLo1);
}

// ============ Phase A: layer-1 scan, thread = (h, b), walks t ============
__global__ __launch_bounds__(256) void scan1_kernel(
    const float* __restrict__ w_syn1, const float* __restrict__ b1)
{
    const int gid = blockIdx.x * 256 + threadIdx.x;
    const int h = gid >> 10;
    const int b = gid & 1023;

    const float inv1 = 1.f / (1.f + expf(-w_syn1[0]));
    const float bh = b1[h];

    const float* Yp = g_YT  + (size_t)h * M_TOT + (size_t)b * T_STEPS;
    float*       Sp = g_SPT + (size_t)h * M_TOT + (size_t)b * T_STEPS;

    float hs = 0.f, v = 0.f;
#pragma unroll 1
    for (int i = 0; i < T_STEPS / 4; ++i) {
        const float4 yv = *reinterpret_cast<const float4*>(Yp + i * 4);
        const float ya[4] = {yv.x, yv.y, yv.z, yv.w};
        float sp[4];
#pragma unroll
        for (int j = 0; j < 4; ++j) {
            hs = (hs - hs * inv1) + ya[j];          // SynapseFilter 1
            const float h1 = hs + bh;
            v = v + (h1 - v) * 0.5f;                // LIF decay (tau=2)
            const float s = (v >= 1.0f) ? 1.f : 0.f;
            v = v * (1.f - s);                      // hard reset
            sp[j] = s;
        }
        *reinterpret_cast<float4*>(Sp + i * 4) =
            make_float4(sp[0], sp[1], sp[2], sp[3]);
    }
}

// ============ Phase B: H2T[o][m] = sum_h SPT[h][m] * W2[o,h] ============
__global__ __launch_bounds__(256) void gemm2_kernel(const float* __restrict__ W2)
{
    __shared__ float w2t[N_HID * N_OUT];
    const int tid = threadIdx.x;
    for (int i = tid; i < N_HID * N_OUT; i += 256) {
        const int o = i / N_HID, h = i % N_HID;
        w2t[h * N_OUT + o] = W2[i];
    }
    __syncthreads();

    const int m = blockIdx.x * 256 + tid;
    float acc[N_OUT];
#pragma unroll
    for (int o = 0; o < N_OUT; ++o) acc[o] = 0.f;

#pragma unroll 4
    for (int h = 0; h < N_HID; ++h) {
        const float v = g_SPT[(size_t)h * M_TOT + m];
#pragma unroll
        for (int o = 0; o < N_OUT; ++o)
            acc[o] = fmaf(v, w2t[h * N_OUT + o], acc[o]);
    }
#pragma unroll
    for (int o = 0; o < N_OUT; ++o)
        g_H2T[(size_t)o * M_TOT + m] = acc[o];
}

// ============ Phase C: layer-2 scan, thread = (o, b) ============
__global__ __launch_bounds__(256) void scan2_kernel(
    const float* __restrict__ w_syn2, const float* __restrict__ b2,
    float* __restrict__ out)
{
    const int gt = blockIdx.x * 256 + threadIdx.x;
    const int o  = gt >> 10;
    const int b  = gt & 1023;

    const float inv2 = 1.f / (1.f + expf(-w_syn2[0]));
    const float bo = b2[o];
    const float* hp = g_H2T + (size_t)o * M_TOT + (size_t)b * T_STEPS;

    float hs = 0.f, v = 0.f;
#pragma unroll 1
    for (int i = 0; i < T_STEPS / 4; ++i) {
        const float4 pv = *reinterpret_cast<const float4*>(hp + i * 4);
        const float pa[4] = {pv.x, pv.y, pv.z, pv.w};
#pragma unroll
        for (int j = 0; j < 4; ++j) {
            hs = (hs - hs * inv2) + pa[j];   // SynapseFilter 2
            const float h2 = hs + bo;
            v = v + (h2 - v) * 0.5f;         // LIF 2 (soft reset @thr 0 -> no-op)
        }
    }
    out[b * N_OUT + o] = v;
}

// ---------------- entry ----------------
extern "C" void kernel_launch(void* const* d_in, const int* in_sizes, int n_in,
                              void* d_out, int out_size) {
    const float* x   = (const float*)d_in[0];  // [1024, 100, 784]
    const float* w1s = (const float*)d_in[1];
    const float* W1  = (const float*)d_in[2];  // [100, 784]
    const float* b1  = (const float*)d_in[3];
    const float* w2s = (const float*)d_in[4];
    const float* W2  = (const float*)d_in[5];  // [10, 100]
    const float* b2  = (const float*)d_in[6];
    float* out = (float*)d_out;                // [1024, 10]

    prep_a_kernel<<<(NKS * 7 * 32 + 255) / 256, 256>>>(W1);
    gemm1_mma_kernel<<<dim3(M_TOT / 256, 2), 256>>>(x);
    scan1_kernel<<<M_TOT / 256, 256>>>(w1s, b1);
    gemm2_kernel<<<M_TOT / 256, 256>>>(W2);
    scan2_kernel<<<(B_BATCH * N_OUT) / 256, 256>>>(w2s, b2, out);
}

// round 9
// speedup vs baseline: 1.8061x; 1.1019x over previous
#include <cuda_runtime.h>
#include <cstdint>
#include <cstddef>

#define B_BATCH 1024
#define T_STEPS 100
#define N_IN    784
#define N_HID   100
#define N_OUT   10
#define M_TOT   (B_BATCH * T_STEPS)   // 102400

#define NKS   98          // 784 / 8 k-steps (k8 each)
#define NCH   49          // 784 / 16 chunks (2 ksteps per chunk)

// Scratch
__device__ float g_YT [(size_t)N_HID * M_TOT];   // Y^T  [100][102400]
__device__ float g_SPT[(size_t)N_HID * M_TOT];   // SP^T [100][102400]
__device__ float g_H2T[(size_t)N_OUT * M_TOT];   // H2^T [10][102400]
// Packed tf32 A-fragments of W1, k-permuted, split by column-half:
// half0: mt 0..3 (cols 0..63), half1: mt 4..6 (cols 64..111, pad >=100)
__device__ float4 g_ApkHi0[NKS * 4 * 32];
__device__ float4 g_ApkLo0[NKS * 4 * 32];
__device__ float4 g_ApkHi1[NKS * 3 * 32];
__device__ float4 g_ApkLo1[NKS * 3 * 32];

// ---------------- tf32 / mma helpers ----------------
static __device__ __forceinline__ uint32_t f2tf32(float x) {
    uint32_t r;
    asm("cvt.rna.tf32.f32 %0, %1;" : "=r"(r) : "f"(x));
    return r;
}
static __device__ __forceinline__ void split_tf32(float x, uint32_t& hi, uint32_t& lo) {
    hi = f2tf32(x);
    lo = f2tf32(x - __uint_as_float(hi));
}
static __device__ __forceinline__ void mma_tf32(
    float& d0, float& d1, float& d2, float& d3,
    uint32_t a0, uint32_t a1, uint32_t a2, uint32_t a3,
    uint32_t b0, uint32_t b1)
{
    asm volatile(
        "mma.sync.aligned.m16n8k8.row.col.f32.tf32.tf32.f32 "
        "{%0,%1,%2,%3}, {%4,%5,%6,%7}, {%8,%9}, {%0,%1,%2,%3};\n"
        : "+f"(d0), "+f"(d1), "+f"(d2), "+f"(d3)
        : "r"(a0), "r"(a1), "r"(a2), "r"(a3), "r"(b0), "r"(b1));
}

// ---------------- cp.async helpers ----------------
static __device__ __forceinline__ uint32_t smem_u32(const void* p) {
    uint32_t a;
    asm("{ .reg .u64 t; cvta.to.shared.u64 t, %1; cvt.u32.u64 %0, t; }"
        : "=r"(a) : "l"(p));
    return a;
}
static __device__ __forceinline__ void cp_async16(uint32_t dst, const void* src) {
    asm volatile("cp.async.ca.shared.global [%0], [%1], 16;"
                 :: "r"(dst), "l"(src) : "memory");
}
static __device__ __forceinline__ void cp_commit() {
    asm volatile("cp.async.commit_group;" ::: "memory");
}
static __device__ __forceinline__ void cp_wait1() {
    asm volatile("cp.async.wait_group 1;" ::: "memory");
}
static __device__ __forceinline__ void cp_wait0() {
    asm volatile("cp.async.wait_group 0;" ::: "memory");
}

// ============ Prep: pack W1 into k-PERMUTED tf32 A-fragments ============
// kstep s2 = 2c+ph covers cols {16c+4r+2ph, 16c+4r+2ph+1} at positions (r, r+4).
__global__ __launch_bounds__(256) void prep_a_kernel(const float* __restrict__ W1)
{
    const int gid = blockIdx.x * 256 + threadIdx.x;
    if (gid >= NKS * 7 * 32) return;
    const int lane = gid & 31;
    const int mt   = (gid >> 5) % 7;
    const int s2   = (gid >> 5) / 7;
    const int q = lane >> 2, r = lane & 3;
    const int c  = s2 >> 1, ph = s2 & 1;

    const int kA = 16 * c + 4 * r + 2 * ph;   // fragment position r
    const int kB = kA + 1;                    // fragment position r+4
    const int n0 = mt * 16 + q;
    const int n1 = n0 + 8;

    const float v0 = (n0 < N_HID) ? W1[(size_t)n0 * N_IN + kA] : 0.f;
    const float v1 = (n1 < N_HID) ? W1[(size_t)n1 * N_IN + kA] : 0.f;
    const float v2 = (n0 < N_HID) ? W1[(size_t)n0 * N_IN + kB] : 0.f;
    const float v3 = (n1 < N_HID) ? W1[(size_t)n1 * N_IN + kB] : 0.f;

    uint32_t h0, l0, h1, l1, h2, l2, h3, l3;
    split_tf32(v0, h0, l0); split_tf32(v1, h1, l1);
    split_tf32(v2, h2, l2); split_tf32(v3, h3, l3);

    float4 fh, fl;
    fh.x = __uint_as_float(h0); fh.y = __uint_as_float(h1);
    fh.z = __uint_as_float(h2); fh.w = __uint_as_float(h3);
    fl.x = __uint_as_float(l0); fl.y = __uint_as_float(l1);
    fl.z = __uint_as_float(l2); fl.w = __uint_as_float(l3);

    if (mt < 4) {
        const int idx = (s2 * 4 + mt) * 32 + lane;
        g_ApkHi0[idx] = fh;
        g_ApkLo0[idx] = fl;
    } else {
        const int idx = (s2 * 3 + (mt - 4)) * 32 + lane;
        g_ApkHi1[idx] = fh;
        g_ApkLo1[idx] = fl;
    }
}

// ============ GEMM1: YT[n][m] = sum_k W1[n,k] X[m,k] (tf32x3) ============
// grid (400, 2): x = 256-row m-block, y = column half. 256 thr, 2 CTA/SM.
// A-fragments staged via cp.async double buffer; X prefetched 1 chunk ahead.
template <int NMTY, int MTBASE>
static __device__ __forceinline__ void gemm_half(
    const float* __restrict__ X,
    const float4* __restrict__ Ah, const float4* __restrict__ Al,
    float4* As)   // smem: 2 buffers x (hi CH + lo CH) float4
{
    constexpr int CH = 2 * NMTY * 32;   // float4 per chunk per (hi|lo)
    const int tid  = threadIdx.x;
    const int warp = tid >> 5;
    const int lane = tid & 31;
    const int q = lane >> 2, r = lane & 3;
    const int m0w = blockIdx.x * 256 + warp * 32;

    float acc[NMTY][4][4];
#pragma unroll
    for (int mt = 0; mt < NMTY; ++mt)
#pragma unroll
        for (int nt = 0; nt < 4; ++nt)
#pragma unroll
            for (int i = 0; i < 4; ++i) acc[mt][nt][i] = 0.f;

    // float4 X pointers: lane reads X[m][16c+4r .. +3] per 16-col chunk
    const float4* xr[4];
#pragma unroll
    for (int nt = 0; nt < 4; ++nt)
        xr[nt] = reinterpret_cast<const float4*>(X)
               + (size_t)(m0w + nt * 8 + q) * (N_IN / 4) + r;

    const uint32_t as_base = smem_u32(As);

    // stage chunk cc into buffer b
    auto stage = [&](int cc, int b) {
        const uint32_t dst = as_base + (uint32_t)(b * 2 * CH) * 16u;
        const float4* srcH = Ah + (size_t)cc * CH;
        const float4* srcL = Al + (size_t)cc * CH;
#pragma unroll
        for (int i = tid; i < CH; i += 256) {
            cp_async16(dst + (uint32_t)i * 16u,        srcH + i);
            cp_async16(dst + (uint32_t)(CH + i) * 16u, srcL + i);
        }
        cp_commit();
    };

    // prologue
    stage(0, 0);
    float4 V[4], Vn[4];
#pragma unroll
    for (int nt = 0; nt < 4; ++nt) V[nt] = xr[nt][0];

    for (int c = 0; c < NCH; ++c) {
        const int b = c & 1;
        if (c + 1 < NCH) { stage(c + 1, b ^ 1); cp_wait1(); }
        else             { cp_wait0(); }
        __syncthreads();

        // prefetch X for next chunk (overlaps this chunk's mma)
        const int cn = (c + 1 < NCH) ? c + 1 : c;
#pragma unroll
        for (int nt = 0; nt < 4; ++nt) Vn[nt] = xr[nt][(size_t)cn * 4];

        const float4* Ab = As + b * 2 * CH;

#pragma unroll
        for (int ph = 0; ph < 2; ++ph) {
            uint32_t bh[4][2], bl[4][2];
#pragma unroll
            for (int nt = 0; nt < 4; ++nt) {
                const float x0 = ph ? V[nt].z : V[nt].x;
                const float x1 = ph ? V[nt].w : V[nt].y;
                split_tf32(x0, bh[nt][0], bl[nt][0]);
                split_tf32(x1, bh[nt][1], bl[nt][1]);
            }

#pragma unroll
            for (int mt = 0; mt < NMTY; ++mt) {
                const float4 ah4 = Ab[(ph * NMTY + mt) * 32 + lane];
                const float4 al4 = Ab[CH + (ph * NMTY + mt) * 32 + lane];
                const uint32_t ah[4] = {
                    __float_as_uint(ah4.x), __float_as_uint(ah4.y),
                    __float_as_uint(ah4.z), __float_as_uint(ah4.w) };
                const uint32_t al[4] = {
                    __float_as_uint(al4.x), __float_as_uint(al4.y),
                    __float_as_uint(al4.z), __float_as_uint(al4.w) };
#pragma unroll
                for (int nt = 0; nt < 4; ++nt)
                    mma_tf32(acc[mt][nt][0], acc[mt][nt][1],
                             acc[mt][nt][2], acc[mt][nt][3],
                             ah[0], ah[1], ah[2], ah[3], bh[nt][0], bh[nt][1]);
#pragma unroll
                for (int nt = 0; nt < 4; ++nt)
                    mma_tf32(acc[mt][nt][0], acc[mt][nt][1],
                             acc[mt][nt][2], acc[mt][nt][3],
                             ah[0], ah[1], ah[2], ah[3], bl[nt][0], bl[nt][1]);
#pragma unroll
                for (int nt = 0; nt < 4; ++nt)
                    mma_tf32(acc[mt][nt][0], acc[mt][nt][1],
                             acc[mt][nt][2], acc[mt][nt][3],
                             al[0], al[1], al[2], al[3], bh[nt][0], bh[nt][1]);
            }
        }

#pragma unroll
        for (int nt = 0; nt < 4; ++nt) V[nt] = Vn[nt];
        __syncthreads();   // all warps done with buffer b before re-staging
    }

    // epilogue -> YT[n][m]
#pragma unroll
    for (int mt = 0; mt < NMTY; ++mt) {
        const int n0 = (MTBASE + mt) * 16 + q;
#pragma unroll
        for (int nt = 0; nt < 4; ++nt) {
            const int m = m0w + nt * 8 + 2 * r;
            if (n0 < N_HID)
                *reinterpret_cast<float2*>(g_YT + (size_t)n0 * M_TOT + m) =
                    make_float2(acc[mt][nt][0], acc[mt][nt][1]);
            if (n0 + 8 < N_HID)
                *reinterpret_cast<float2*>(g_YT + (size_t)(n0 + 8) * M_TOT + m) =
                    make_float2(acc[mt][nt][2], acc[mt][nt][3]);
        }
    }
}

__global__ __launch_bounds__(256, 2) void gemm1_mma_kernel(const float* __restrict__ X)
{
    // max over halves: NMTY=4 -> 2 buffers x 2 x CH(256) float4 = 16 KB
    __shared__ float4 As[2 * 2 * (2 * 4 * 32)];
    if (blockIdx.y == 0)
        gemm_half<4, 0>(X, g_ApkHi0, g_ApkLo0, As);
    else
        gemm_half<3, 4>(X, g_ApkHi1, g_ApkLo1, As);
}

// ============ Phase A: layer-1 scan, thread = (h, b), walks t ============
__global__ __launch_bounds__(256) void scan1_kernel(
    const float* __restrict__ w_syn1, const float* __restrict__ b1)
{
    const int gid = blockIdx.x * 256 + threadIdx.x;
    const int h = gid >> 10;
    const int b = gid & 1023;

    const float inv1 = 1.f / (1.f + expf(-w_syn1[0]));
    const float bh = b1[h];

    const float* Yp = g_YT  + (size_t)h * M_TOT + (size_t)b * T_STEPS;
    float*       Sp = g_SPT + (size_t)h * M_TOT + (size_t)b * T_STEPS;

    float hs = 0.f, v = 0.f;
#pragma unroll 1
    for (int i = 0; i < T_STEPS / 4; ++i) {
        const float4 yv = *reinterpret_cast<const float4*>(Yp + i * 4);
        const float ya[4] = {yv.x, yv.y, yv.z, yv.w};
        float sp[4];
#pragma unroll
        for (int j = 0; j < 4; ++j) {
            hs = (hs - hs * inv1) + ya[j];          // SynapseFilter 1
            const float h1 = hs + bh;
            v = v + (h1 - v) * 0.5f;                // LIF decay (tau=2)
            const float s = (v >= 1.0f) ? 1.f : 0.f;
            v = v * (1.f - s);                      // hard reset
            sp[j] = s;
        }
        *reinterpret_cast<float4*>(Sp + i * 4) =
            make_float4(sp[0], sp[1], sp[2], sp[3]);
    }
}

// ============ Phase B: H2T[o][m] = sum_h SPT[h][m] * W2[o,h] ============
__global__ __launch_bounds__(256) void gemm2_kernel(const float* __restrict__ W2)
{
    __shared__ float w2t[N_HID * N_OUT];
    const int tid = threadIdx.x;
    for (int i = tid; i < N_HID * N_OUT; i += 256) {
        const int o = i / N_HID, h = i % N_HID;
        w2t[h * N_OUT + o] = W2[i];
    }
    __syncthreads();

    const int m = blockIdx.x * 256 + tid;
    float acc[N_OUT];
#pragma unroll
    for (int o = 0; o < N_OUT; ++o) acc[o] = 0.f;

#pragma unroll 4
    for (int h = 0; h < N_HID; ++h) {
        const float v = g_SPT[(size_t)h * M_TOT + m];
#pragma unroll
        for (int o = 0; o < N_OUT; ++o)
            acc[o] = fmaf(v, w2t[h * N_OUT + o], acc[o]);
    }
#pragma unroll
    for (int o = 0; o < N_OUT; ++o)
        g_H2T[(size_t)o * M_TOT + m] = acc[o];
}

// ============ Phase C: layer-2 scan, thread = (o, b) ============
__global__ __launch_bounds__(256) void scan2_kernel(
    const float* __restrict__ w_syn2, const float* __restrict__ b2,
    float* __restrict__ out)
{
    const int gt = blockIdx.x * 256 + threadIdx.x;
    const int o  = gt >> 10;
    const int b  = gt & 1023;

    const float inv2 = 1.f / (1.f + expf(-w_syn2[0]));
    const float bo = b2[o];
    const float* hp = g_H2T + (size_t)o * M_TOT + (size_t)b * T_STEPS;

    float hs = 0.f, v = 0.f;
#pragma unroll 1
    for (int i = 0; i < T_STEPS / 4; ++i) {
        const float4 pv = *reinterpret_cast<const float4*>(hp + i * 4);
        const float pa[4] = {pv.x, pv.y, pv.z, pv.w};
#pragma unroll
        for (int j = 0; j < 4; ++j) {
            hs = (hs - hs * inv2) + pa[j];   // SynapseFilter 2
            const float h2 = hs + bo;
            v = v + (h2 - v) * 0.5f;         // LIF 2 (soft reset @thr 0 -> no-op)
        }
    }
    out[b * N_OUT + o] = v;
}

// ---------------- entry ----------------
extern "C" void kernel_launch(void* const* d_in, const int* in_sizes, int n_in,
                              void* d_out, int out_size) {
    const float* x   = (const float*)d_in[0];  // [1024, 100, 784]
    const float* w1s = (const float*)d_in[1];
    const float* W1  = (const float*)d_in[2];  // [100, 784]
    const float* b1  = (const float*)d_in[3];
    const float* w2s = (const float*)d_in[4];
    const float* W2  = (const float*)d_in[5];  // [10, 100]
    const float* b2  = (const float*)d_in[6];
    float* out = (float*)d_out;                // [1024, 10]

    prep_a_kernel<<<(NKS * 7 * 32 + 255) / 256, 256>>>(W1);
    gemm1_mma_kernel<<<dim3(M_TOT / 256, 2), 256>>>(x);
    scan1_kernel<<<M_TOT / 256, 256>>>(w1s, b1);
    gemm2_kernel<<<M_TOT / 256, 256>>>(W2);
    scan2_kernel<<<(B_BATCH * N_OUT) / 256, 256>>>(w2s, b2, out);
}

// round 10
// speedup vs baseline: 1.8606x; 1.0302x over previous
#include <cuda_runtime.h>
#include <cstdint>
#include <cstddef>

#define B_BATCH 1024
#define T_STEPS 100
#define N_IN    784
#define N_HID   100
#define N_OUT   10
#define M_TOT   (B_BATCH * T_STEPS)   // 102400

#define NKS   98          // 784 / 8 k-steps (k8 each)
#define NCH   49          // 784 / 16 chunks (2 ksteps per chunk)

// Scratch
__device__ float g_YT [(size_t)N_HID * M_TOT];     // Y^T  [100][102400]
__device__ uint4 g_SPB[(size_t)N_HID * B_BATCH];   // spike bits [h][b] -> 128 t-bits
__device__ float g_H2T[(size_t)N_OUT * M_TOT];     // H2^T [10][102400]
// Packed tf32 A-fragments of W1, k-permuted, split by column-half:
__device__ float4 g_ApkHi0[NKS * 4 * 32];
__device__ float4 g_ApkLo0[NKS * 4 * 32];
__device__ float4 g_ApkHi1[NKS * 3 * 32];
__device__ float4 g_ApkLo1[NKS * 3 * 32];

// ---------------- tf32 / mma helpers ----------------
static __device__ __forceinline__ uint32_t f2tf32(float x) {
    uint32_t r;
    asm("cvt.rna.tf32.f32 %0, %1;" : "=r"(r) : "f"(x));
    return r;
}
static __device__ __forceinline__ void split_tf32(float x, uint32_t& hi, uint32_t& lo) {
    hi = f2tf32(x);
    lo = f2tf32(x - __uint_as_float(hi));
}
static __device__ __forceinline__ void mma_tf32(
    float& d0, float& d1, float& d2, float& d3,
    uint32_t a0, uint32_t a1, uint32_t a2, uint32_t a3,
    uint32_t b0, uint32_t b1)
{
    asm volatile(
        "mma.sync.aligned.m16n8k8.row.col.f32.tf32.tf32.f32 "
        "{%0,%1,%2,%3}, {%4,%5,%6,%7}, {%8,%9}, {%0,%1,%2,%3};\n"
        : "+f"(d0), "+f"(d1), "+f"(d2), "+f"(d3)
        : "r"(a0), "r"(a1), "r"(a2), "r"(a3), "r"(b0), "r"(b1));
}

// ---------------- cp.async helpers ----------------
static __device__ __forceinline__ uint32_t smem_u32(const void* p) {
    uint32_t a;
    asm("{ .reg .u64 t; cvta.to.shared.u64 t, %1; cvt.u32.u64 %0, t; }"
        : "=r"(a) : "l"(p));
    return a;
}
static __device__ __forceinline__ void cp_async16(uint32_t dst, const void* src) {
    asm volatile("cp.async.ca.shared.global [%0], [%1], 16;"
                 :: "r"(dst), "l"(src) : "memory");
}
static __device__ __forceinline__ void cp_commit() {
    asm volatile("cp.async.commit_group;" ::: "memory");
}
static __device__ __forceinline__ void cp_wait1() {
    asm volatile("cp.async.wait_group 1;" ::: "memory");
}
static __device__ __forceinline__ void cp_wait0() {
    asm volatile("cp.async.wait_group 0;" ::: "memory");
}

// ============ Prep: pack W1 into k-PERMUTED tf32 A-fragments ============
__global__ __launch_bounds__(256) void prep_a_kernel(const float* __restrict__ W1)
{
    const int gid = blockIdx.x * 256 + threadIdx.x;
    if (gid >= NKS * 7 * 32) return;
    const int lane = gid & 31;
    const int mt   = (gid >> 5) % 7;
    const int s2   = (gid >> 5) / 7;
    const int q = lane >> 2, r = lane & 3;
    const int c  = s2 >> 1, ph = s2 & 1;

    const int kA = 16 * c + 4 * r + 2 * ph;
    const int kB = kA + 1;
    const int n0 = mt * 16 + q;
    const int n1 = n0 + 8;

    const float v0 = (n0 < N_HID) ? W1[(size_t)n0 * N_IN + kA] : 0.f;
    const float v1 = (n1 < N_HID) ? W1[(size_t)n1 * N_IN + kA] : 0.f;
    const float v2 = (n0 < N_HID) ? W1[(size_t)n0 * N_IN + kB] : 0.f;
    const float v3 = (n1 < N_HID) ? W1[(size_t)n1 * N_IN + kB] : 0.f;

    uint32_t h0, l0, h1, l1, h2, l2, h3, l3;
    split_tf32(v0, h0, l0); split_tf32(v1, h1, l1);
    split_tf32(v2, h2, l2); split_tf32(v3, h3, l3);

    float4 fh, fl;
    fh.x = __uint_as_float(h0); fh.y = __uint_as_float(h1);
    fh.z = __uint_as_float(h2); fh.w = __uint_as_float(h3);
    fl.x = __uint_as_float(l0); fl.y = __uint_as_float(l1);
    fl.z = __uint_as_float(l2); fl.w = __uint_as_float(l3);

    if (mt < 4) {
        const int idx = (s2 * 4 + mt) * 32 + lane;
        g_ApkHi0[idx] = fh;
        g_ApkLo0[idx] = fl;
    } else {
        const int idx = (s2 * 3 + (mt - 4)) * 32 + lane;
        g_ApkHi1[idx] = fh;
        g_ApkLo1[idx] = fl;
    }
}

// ============ GEMM1: YT[n][m] = sum_k W1[n,k] X[m,k] (tf32x3) ============
template <int NMTY, int MTBASE>
static __device__ __forceinline__ void gemm_half(
    const float* __restrict__ X,
    const float4* __restrict__ Ah, const float4* __restrict__ Al,
    float4* As)
{
    constexpr int CH = 2 * NMTY * 32;
    const int tid  = threadIdx.x;
    const int warp = tid >> 5;
    const int lane = tid & 31;
    const int q = lane >> 2, r = lane & 3;
    const int m0w = blockIdx.x * 256 + warp * 32;

    float acc[NMTY][4][4];
#pragma unroll
    for (int mt = 0; mt < NMTY; ++mt)
#pragma unroll
        for (int nt = 0; nt < 4; ++nt)
#pragma unroll
            for (int i = 0; i < 4; ++i) acc[mt][nt][i] = 0.f;

    const float4* xr[4];
#pragma unroll
    for (int nt = 0; nt < 4; ++nt)
        xr[nt] = reinterpret_cast<const float4*>(X)
               + (size_t)(m0w + nt * 8 + q) * (N_IN / 4) + r;

    const uint32_t as_base = smem_u32(As);

    auto stage = [&](int cc, int b) {
        const uint32_t dst = as_base + (uint32_t)(b * 2 * CH) * 16u;
        const float4* srcH = Ah + (size_t)cc * CH;
        const float4* srcL = Al + (size_t)cc * CH;
#pragma unroll
        for (int i = tid; i < CH; i += 256) {
            cp_async16(dst + (uint32_t)i * 16u,        srcH + i);
            cp_async16(dst + (uint32_t)(CH + i) * 16u, srcL + i);
        }
        cp_commit();
    };

    stage(0, 0);
    float4 V[4], Vn[4];
#pragma unroll
    for (int nt = 0; nt < 4; ++nt) V[nt] = xr[nt][0];

    for (int c = 0; c < NCH; ++c) {
        const int b = c & 1;
        if (c + 1 < NCH) { stage(c + 1, b ^ 1); cp_wait1(); }
        else             { cp_wait0(); }
        __syncthreads();

        const int cn = (c + 1 < NCH) ? c + 1 : c;
#pragma unroll
        for (int nt = 0; nt < 4; ++nt) Vn[nt] = xr[nt][(size_t)cn * 4];

        const float4* Ab = As + b * 2 * CH;

#pragma unroll
        for (int ph = 0; ph < 2; ++ph) {
            uint32_t bh[4][2], bl[4][2];
#pragma unroll
            for (int nt = 0; nt < 4; ++nt) {
                const float x0 = ph ? V[nt].z : V[nt].x;
                const float x1 = ph ? V[nt].w : V[nt].y;
                split_tf32(x0, bh[nt][0], bl[nt][0]);
                split_tf32(x1, bh[nt][1], bl[nt][1]);
            }

#pragma unroll
            for (int mt = 0; mt < NMTY; ++mt) {
                const float4 ah4 = Ab[(ph * NMTY + mt) * 32 + lane];
                const float4 al4 = Ab[CH + (ph * NMTY + mt) * 32 + lane];
                const uint32_t ah[4] = {
                    __float_as_uint(ah4.x), __float_as_uint(ah4.y),
                    __float_as_uint(ah4.z), __float_as_uint(ah4.w) };
                const uint32_t al[4] = {
                    __float_as_uint(al4.x), __float_as_uint(al4.y),
                    __float_as_uint(al4.z), __float_as_uint(al4.w) };
#pragma unroll
                for (int nt = 0; nt < 4; ++nt)
                    mma_tf32(acc[mt][nt][0], acc[mt][nt][1],
                             acc[mt][nt][2], acc[mt][nt][3],
                             ah[0], ah[1], ah[2], ah[3], bh[nt][0], bh[nt][1]);
#pragma unroll
                for (int nt = 0; nt < 4; ++nt)
                    mma_tf32(acc[mt][nt][0], acc[mt][nt][1],
                             acc[mt][nt][2], acc[mt][nt][3],
                             ah[0], ah[1], ah[2], ah[3], bl[nt][0], bl[nt][1]);
#pragma unroll
                for (int nt = 0; nt < 4; ++nt)
                    mma_tf32(acc[mt][nt][0], acc[mt][nt][1],
                             acc[mt][nt][2], acc[mt][nt][3],
                             al[0], al[1], al[2], al[3], bh[nt][0], bh[nt][1]);
            }
        }

#pragma unroll
        for (int nt = 0; nt < 4; ++nt) V[nt] = Vn[nt];
        __syncthreads();
    }

#pragma unroll
    for (int mt = 0; mt < NMTY; ++mt) {
        const int n0 = (MTBASE + mt) * 16 + q;
#pragma unroll
        for (int nt = 0; nt < 4; ++nt) {
            const int m = m0w + nt * 8 + 2 * r;
            if (n0 < N_HID)
                *reinterpret_cast<float2*>(g_YT + (size_t)n0 * M_TOT + m) =
                    make_float2(acc[mt][nt][0], acc[mt][nt][1]);
            if (n0 + 8 < N_HID)
                *reinterpret_cast<float2*>(g_YT + (size_t)(n0 + 8) * M_TOT + m) =
                    make_float2(acc[mt][nt][2], acc[mt][nt][3]);
        }
    }
}

__global__ __launch_bounds__(256, 2) void gemm1_mma_kernel(const float* __restrict__ X)
{
    __shared__ float4 As[2 * 2 * (2 * 4 * 32)];
    if (blockIdx.y == 0)
        gemm_half<4, 0>(X, g_ApkHi0, g_ApkLo0, As);
    else
        gemm_half<3, 4>(X, g_ApkHi1, g_ApkLo1, As);
}

// ============ Phase A: layer-1 scan -> bit-packed spikes ============
// thread = (h, b); packs 100 t-bits into uint4 (bits t&31 of word t>>5)
__global__ __launch_bounds__(256) void scan1_kernel(
    const float* __restrict__ w_syn1, const float* __restrict__ b1)
{
    const int gid = blockIdx.x * 256 + threadIdx.x;   // 0..102399
    const int h = gid >> 10;
    const int b = gid & 1023;

    const float inv1 = 1.f / (1.f + expf(-w_syn1[0]));
    const float bh = b1[h];

    const float* Yp = g_YT + (size_t)h * M_TOT + (size_t)b * T_STEPS;

    float hs = 0.f, v = 0.f;
    uint32_t w[4] = {0u, 0u, 0u, 0u};

#pragma unroll 1
    for (int i = 0; i < T_STEPS / 4; ++i) {
        const float4 yv = *reinterpret_cast<const float4*>(Yp + i * 4);
        const float ya[4] = {yv.x, yv.y, yv.z, yv.w};
#pragma unroll
        for (int j = 0; j < 4; ++j) {
            hs = (hs - hs * inv1) + ya[j];          // SynapseFilter 1
            const float h1 = hs + bh;
            v = v + (h1 - v) * 0.5f;                // LIF decay (tau=2)
            const int t = i * 4 + j;
            if (v >= 1.0f) {
                w[t >> 5] |= (1u << (t & 31));
                v = 0.f;                            // hard reset
            }
        }
    }
    g_SPB[(size_t)h * B_BATCH + b] = make_uint4(w[0], w[1], w[2], w[3]);
}

// ============ Phase B: H2T[o][m] = sum_h sp[h][m] * W2[o,h] (bits) ============
__global__ __launch_bounds__(256) void gemm2_kernel(const float* __restrict__ W2)
{
    __shared__ float w2t[N_HID * N_OUT];   // w2t[h*10+o]
    const int tid = threadIdx.x;
    for (int i = tid; i < N_HID * N_OUT; i += 256) {
        const int o = i / N_HID, h = i % N_HID;
        w2t[h * N_OUT + o] = W2[i];
    }
    __syncthreads();

    const int m = blockIdx.x * 256 + tid;
    const int b = m / T_STEPS;
    const int t = m - b * T_STEPS;
    const int wrd = t >> 5;
    const int bit = t & 31;

    const uint32_t* sp = reinterpret_cast<const uint32_t*>(g_SPB) + (size_t)b * 4 + wrd;

    float acc[N_OUT];
#pragma unroll
    for (int o = 0; o < N_OUT; ++o) acc[o] = 0.f;

#pragma unroll 4
    for (int h = 0; h < N_HID; ++h) {
        const uint32_t word = sp[(size_t)h * B_BATCH * 4];
        const float v = (float)((word >> bit) & 1u);
#pragma unroll
        for (int o = 0; o < N_OUT; ++o)
            acc[o] = fmaf(v, w2t[h * N_OUT + o], acc[o]);
    }
#pragma unroll
    for (int o = 0; o < N_OUT; ++o)
        g_H2T[(size_t)o * M_TOT + m] = acc[o];
}

// ============ Phase C: layer-2 scan, thread = (o, b) ============
__global__ __launch_bounds__(64) void scan2_kernel(
    const float* __restrict__ w_syn2, const float* __restrict__ b2,
    float* __restrict__ out)
{
    const int gt = blockIdx.x * 64 + threadIdx.x;   // 0..10239
    const int o  = gt >> 10;
    const int b  = gt & 1023;

    const float inv2 = 1.f / (1.f + expf(-w_syn2[0]));
    const float bo = b2[o];
    const float* hp = g_H2T + (size_t)o * M_TOT + (size_t)b * T_STEPS;

    float hs = 0.f, v = 0.f;
    float4 cur = *reinterpret_cast<const float4*>(hp);
#pragma unroll 1
    for (int i = 0; i < T_STEPS / 4; ++i) {
        const float4 nxt = (i + 1 < T_STEPS / 4)
            ? *reinterpret_cast<const float4*>(hp + (i + 1) * 4)
            : make_float4(0.f, 0.f, 0.f, 0.f);
        const float pa[4] = {cur.x, cur.y, cur.z, cur.w};
#pragma unroll
        for (int j = 0; j < 4; ++j) {
            hs = (hs - hs * inv2) + pa[j];   // SynapseFilter 2
            const float h2 = hs + bo;
            v = v + (h2 - v) * 0.5f;         // LIF 2 (soft reset @thr 0 -> no-op)
        }
        cur = nxt;
    }
    out[b * N_OUT + o] = v;
}

// ---------------- entry ----------------
extern "C" void kernel_launch(void* const* d_in, const int* in_sizes, int n_in,
                              void* d_out, int out_size) {
    const float* x   = (const float*)d_in[0];  // [1024, 100, 784]
    const float* w1s = (const float*)d_in[1];
    const float* W1  = (const float*)d_in[2];  // [100, 784]
    const float* b1  = (const float*)d_in[3];
    const float* w2s = (const float*)d_in[4];
    const float* W2  = (const float*)d_in[5];  // [10, 100]
    const float* b2  = (const float*)d_in[6];
    float* out = (float*)d_out;                // [1024, 10]

    prep_a_kernel<<<(NKS * 7 * 32 + 255) / 256, 256>>>(W1);
    gemm1_mma_kernel<<<dim3(M_TOT / 256, 2), 256>>>(x);
    scan1_kernel<<<M_TOT / 256, 256>>>(w1s, b1);
    gemm2_kernel<<<M_TOT / 256, 256>>>(W2);
    scan2_kernel<<<(B_BATCH * N_OUT) / 64, 64>>>(w2s, b2, out);
}

// round 11
// speedup vs baseline: 1.9948x; 1.0721x over previous
#include <cuda_runtime.h>
#include <cstdint>
#include <cstddef>

#define B_BATCH 1024
#define T_STEPS 100
#define N_IN    784
#define N_HID   100
#define N_OUT   10
#define M_TOT   (B_BATCH * T_STEPS)   // 102400

#define NKS   98          // 784 / 8 k-steps (k8 each)
#define NCH   49          // 784 / 16 chunks (2 ksteps per chunk)

// Scratch
__device__ float g_YT [(size_t)N_HID * M_TOT];     // Y^T  [100][102400]
// Packed tf32 A-fragments of W1, k-permuted, split by column-half:
__device__ float4 g_ApkHi0[NKS * 4 * 32];
__device__ float4 g_ApkLo0[NKS * 4 * 32];
__device__ float4 g_ApkHi1[NKS * 3 * 32];
__device__ float4 g_ApkLo1[NKS * 3 * 32];

// ---------------- tf32 / mma helpers ----------------
static __device__ __forceinline__ uint32_t f2tf32(float x) {
    uint32_t r;
    asm("cvt.rna.tf32.f32 %0, %1;" : "=r"(r) : "f"(x));
    return r;
}
static __device__ __forceinline__ void split_tf32(float x, uint32_t& hi, uint32_t& lo) {
    hi = f2tf32(x);
    lo = f2tf32(x - __uint_as_float(hi));
}
static __device__ __forceinline__ void mma_tf32(
    float& d0, float& d1, float& d2, float& d3,
    uint32_t a0, uint32_t a1, uint32_t a2, uint32_t a3,
    uint32_t b0, uint32_t b1)
{
    asm volatile(
        "mma.sync.aligned.m16n8k8.row.col.f32.tf32.tf32.f32 "
        "{%0,%1,%2,%3}, {%4,%5,%6,%7}, {%8,%9}, {%0,%1,%2,%3};\n"
        : "+f"(d0), "+f"(d1), "+f"(d2), "+f"(d3)
        : "r"(a0), "r"(a1), "r"(a2), "r"(a3), "r"(b0), "r"(b1));
}

// ---------------- cp.async helpers ----------------
static __device__ __forceinline__ uint32_t smem_u32(const void* p) {
    uint32_t a;
    asm("{ .reg .u64 t; cvta.to.shared.u64 t, %1; cvt.u32.u64 %0, t; }"
        : "=r"(a) : "l"(p));
    return a;
}
static __device__ __forceinline__ void cp_async16(uint32_t dst, const void* src) {
    asm volatile("cp.async.ca.shared.global [%0], [%1], 16;"
                 :: "r"(dst), "l"(src) : "memory");
}
static __device__ __forceinline__ void cp_commit() {
    asm volatile("cp.async.commit_group;" ::: "memory");
}
static __device__ __forceinline__ void cp_wait1() {
    asm volatile("cp.async.wait_group 1;" ::: "memory");
}
static __device__ __forceinline__ void cp_wait0() {
    asm volatile("cp.async.wait_group 0;" ::: "memory");
}

// ============ Prep: pack W1 into k-PERMUTED tf32 A-fragments ============
__global__ __launch_bounds__(256) void prep_a_kernel(const float* __restrict__ W1)
{
    const int gid = blockIdx.x * 256 + threadIdx.x;
    if (gid >= NKS * 7 * 32) return;
    const int lane = gid & 31;
    const int mt   = (gid >> 5) % 7;
    const int s2   = (gid >> 5) / 7;
    const int q = lane >> 2, r = lane & 3;
    const int c  = s2 >> 1, ph = s2 & 1;

    const int kA = 16 * c + 4 * r + 2 * ph;
    const int kB = kA + 1;
    const int n0 = mt * 16 + q;
    const int n1 = n0 + 8;

    const float v0 = (n0 < N_HID) ? W1[(size_t)n0 * N_IN + kA] : 0.f;
    const float v1 = (n1 < N_HID) ? W1[(size_t)n1 * N_IN + kA] : 0.f;
    const float v2 = (n0 < N_HID) ? W1[(size_t)n0 * N_IN + kB] : 0.f;
    const float v3 = (n1 < N_HID) ? W1[(size_t)n1 * N_IN + kB] : 0.f;

    uint32_t h0, l0, h1, l1, h2, l2, h3, l3;
    split_tf32(v0, h0, l0); split_tf32(v1, h1, l1);
    split_tf32(v2, h2, l2); split_tf32(v3, h3, l3);

    float4 fh, fl;
    fh.x = __uint_as_float(h0); fh.y = __uint_as_float(h1);
    fh.z = __uint_as_float(h2); fh.w = __uint_as_float(h3);
    fl.x = __uint_as_float(l0); fl.y = __uint_as_float(l1);
    fl.z = __uint_as_float(l2); fl.w = __uint_as_float(l3);

    if (mt < 4) {
        const int idx = (s2 * 4 + mt) * 32 + lane;
        g_ApkHi0[idx] = fh;
        g_ApkLo0[idx] = fl;
    } else {
        const int idx = (s2 * 3 + (mt - 4)) * 32 + lane;
        g_ApkHi1[idx] = fh;
        g_ApkLo1[idx] = fl;
    }
}

// ============ GEMM1: YT[n][m] = sum_k W1[n,k] X[m,k] (tf32x3) ============
// grid (800, 2): x = 128-row m-block, y = column half. 256 thr, 3 CTA/SM.
// Warp covers 16 m-rows (nt=0,1); A staged via cp.async; X prefetch 1 chunk.
template <int NMTY, int MTBASE>
static __device__ __forceinline__ void gemm_half(
    const float* __restrict__ X,
    const float4* __restrict__ Ah, const float4* __restrict__ Al,
    float4* As)
{
    constexpr int CH = 2 * NMTY * 32;
    const int tid  = threadIdx.x;
    const int warp = tid >> 5;
    const int lane = tid & 31;
    const int q = lane >> 2, r = lane & 3;
    const int m0w = blockIdx.x * 128 + warp * 16;

    float acc[NMTY][2][4];
#pragma unroll
    for (int mt = 0; mt < NMTY; ++mt)
#pragma unroll
        for (int nt = 0; nt < 2; ++nt)
#pragma unroll
            for (int i = 0; i < 4; ++i) acc[mt][nt][i] = 0.f;

    const float4* xr[2];
#pragma unroll
    for (int nt = 0; nt < 2; ++nt)
        xr[nt] = reinterpret_cast<const float4*>(X)
               + (size_t)(m0w + nt * 8 + q) * (N_IN / 4) + r;

    const uint32_t as_base = smem_u32(As);

    auto stage = [&](int cc, int b) {
        const uint32_t dst = as_base + (uint32_t)(b * 2 * CH) * 16u;
        const float4* srcH = Ah + (size_t)cc * CH;
        const float4* srcL = Al + (size_t)cc * CH;
#pragma unroll
        for (int i = tid; i < CH; i += 256) {
            cp_async16(dst + (uint32_t)i * 16u,        srcH + i);
            cp_async16(dst + (uint32_t)(CH + i) * 16u, srcL + i);
        }
        cp_commit();
    };

    stage(0, 0);
    float4 V[2], Vn[2];
#pragma unroll
    for (int nt = 0; nt < 2; ++nt) V[nt] = xr[nt][0];

    for (int c = 0; c < NCH; ++c) {
        const int b = c & 1;
        if (c + 1 < NCH) { stage(c + 1, b ^ 1); cp_wait1(); }
        else             { cp_wait0(); }
        __syncthreads();

        const int cn = (c + 1 < NCH) ? c + 1 : c;
#pragma unroll
        for (int nt = 0; nt < 2; ++nt) Vn[nt] = xr[nt][(size_t)cn * 4];

        const float4* Ab = As + b * 2 * CH;

#pragma unroll
        for (int ph = 0; ph < 2; ++ph) {
            uint32_t bh[2][2], bl[2][2];
#pragma unroll
            for (int nt = 0; nt < 2; ++nt) {
                const float x0 = ph ? V[nt].z : V[nt].x;
                const float x1 = ph ? V[nt].w : V[nt].y;
                split_tf32(x0, bh[nt][0], bl[nt][0]);
                split_tf32(x1, bh[nt][1], bl[nt][1]);
            }

#pragma unroll
            for (int mt = 0; mt < NMTY; ++mt) {
                const float4 ah4 = Ab[(ph * NMTY + mt) * 32 + lane];
                const float4 al4 = Ab[CH + (ph * NMTY + mt) * 32 + lane];
                const uint32_t ah[4] = {
                    __float_as_uint(ah4.x), __float_as_uint(ah4.y),
                    __float_as_uint(ah4.z), __float_as_uint(ah4.w) };
                const uint32_t al[4] = {
                    __float_as_uint(al4.x), __float_as_uint(al4.y),
                    __float_as_uint(al4.z), __float_as_uint(al4.w) };
#pragma unroll
                for (int nt = 0; nt < 2; ++nt)
                    mma_tf32(acc[mt][nt][0], acc[mt][nt][1],
                             acc[mt][nt][2], acc[mt][nt][3],
                             ah[0], ah[1], ah[2], ah[3], bh[nt][0], bh[nt][1]);
#pragma unroll
                for (int nt = 0; nt < 2; ++nt)
                    mma_tf32(acc[mt][nt][0], acc[mt][nt][1],
                             acc[mt][nt][2], acc[mt][nt][3],
                             ah[0], ah[1], ah[2], ah[3], bl[nt][0], bl[nt][1]);
#pragma unroll
                for (int nt = 0; nt < 2; ++nt)
                    mma_tf32(acc[mt][nt][0], acc[mt][nt][1],
                             acc[mt][nt][2], acc[mt][nt][3],
                             al[0], al[1], al[2], al[3], bh[nt][0], bh[nt][1]);
            }
        }

#pragma unroll
        for (int nt = 0; nt < 2; ++nt) V[nt] = Vn[nt];
        __syncthreads();
    }

#pragma unroll
    for (int mt = 0; mt < NMTY; ++mt) {
        const int n0 = (MTBASE + mt) * 16 + q;
#pragma unroll
        for (int nt = 0; nt < 2; ++nt) {
            const int m = m0w + nt * 8 + 2 * r;
            if (n0 < N_HID)
                *reinterpret_cast<float2*>(g_YT + (size_t)n0 * M_TOT + m) =
                    make_float2(acc[mt][nt][0], acc[mt][nt][1]);
            if (n0 + 8 < N_HID)
                *reinterpret_cast<float2*>(g_YT + (size_t)(n0 + 8) * M_TOT + m) =
                    make_float2(acc[mt][nt][2], acc[mt][nt][3]);
        }
    }
}

__global__ __launch_bounds__(256, 3) void gemm1_mma_kernel(const float* __restrict__ X)
{
    __shared__ float4 As[2 * 2 * (2 * 4 * 32)];   // 16 KB (max half)
    if (blockIdx.y == 0)
        gemm_half<4, 0>(X, g_ApkHi0, g_ApkLo0, As);
    else
        gemm_half<3, 4>(X, g_ApkHi1, g_ApkLo1, As);
}

// ============ Fused SNN: scan1 + gemm2 + scan2, one block per batch b ======
__global__ __launch_bounds__(128) void snn_fused_kernel(
    const float* __restrict__ w_syn1, const float* __restrict__ b1,
    const float* __restrict__ w_syn2, const float* __restrict__ W2,
    const float* __restrict__ b2, float* __restrict__ out)
{
    __shared__ float    w2s[N_HID * N_OUT];    // [h*10+o]
    __shared__ uint32_t spw[N_HID * 4];        // spike bits [h][word]
    __shared__ float    h2s[N_OUT * T_STEPS];  // [o*100+t]

    const int b   = blockIdx.x;
    const int tid = threadIdx.x;

    for (int i = tid; i < N_HID * N_OUT; i += 128) {
        const int o = i / N_HID, h = i % N_HID;
        w2s[h * N_OUT + o] = W2[i];
    }

    // ---- phase 1: layer-1 scan, thread = h ----
    if (tid < N_HID) {
        const int h = tid;
        const float inv1 = 1.f / (1.f + expf(-w_syn1[0]));
        const float bh = b1[h];
        const float* Yp = g_YT + (size_t)h * M_TOT + (size_t)b * T_STEPS;

        float hs = 0.f, v = 0.f;
        uint32_t w[4] = {0u, 0u, 0u, 0u};
#pragma unroll 1
        for (int i = 0; i < T_STEPS / 4; ++i) {
            const float4 yv = *reinterpret_cast<const float4*>(Yp + i * 4);
            const float ya[4] = {yv.x, yv.y, yv.z, yv.w};
#pragma unroll
            for (int j = 0; j < 4; ++j) {
                hs = (hs - hs * inv1) + ya[j];          // SynapseFilter 1
                const float h1 = hs + bh;
                v = v + (h1 - v) * 0.5f;                // LIF decay (tau=2)
                const int t = i * 4 + j;
                if (v >= 1.0f) {
                    w[t >> 5] |= (1u << (t & 31));
                    v = 0.f;                            // hard reset
                }
            }
        }
#pragma unroll
        for (int k = 0; k < 4; ++k) spw[h * 4 + k] = w[k];
    }
    __syncthreads();

    // ---- phase 2: H2[o][t] = sum_h bit(h,t) * W2[o,h], thread = t ----
    if (tid < T_STEPS) {
        const int t = tid;
        const int wrd = t >> 5, bit = t & 31;
        float acc[N_OUT];
#pragma unroll
        for (int o = 0; o < N_OUT; ++o) acc[o] = 0.f;
#pragma unroll 4
        for (int h = 0; h < N_HID; ++h) {
            const uint32_t word = spw[h * 4 + wrd];
            const float v = (float)((word >> bit) & 1u);
#pragma unroll
            for (int o = 0; o < N_OUT; ++o)
                acc[o] = fmaf(v, w2s[h * N_OUT + o], acc[o]);
        }
#pragma unroll
        for (int o = 0; o < N_OUT; ++o) h2s[o * T_STEPS + t] = acc[o];
    }
    __syncthreads();

    // ---- phase 3: layer-2 scan, thread = o ----
    if (tid < N_OUT) {
        const int o = tid;
        const float inv2 = 1.f / (1.f + expf(-w_syn2[0]));
        const float bo = b2[o];
        const float* hp = h2s + o * T_STEPS;

        float hs = 0.f, v = 0.f;
#pragma unroll 4
        for (int t = 0; t < T_STEPS; ++t) {
            const float p = hp[t];
            hs = (hs - hs * inv2) + p;   // SynapseFilter 2
            const float h2 = hs + bo;
            v = v + (h2 - v) * 0.5f;     // LIF 2 (soft reset @thr 0 -> no-op)
        }
        out[b * N_OUT + o] = v;
    }
}

// ---------------- entry ----------------
extern "C" void kernel_launch(void* const* d_in, const int* in_sizes, int n_in,
                              void* d_out, int out_size) {
    const float* x   = (const float*)d_in[0];  // [1024, 100, 784]
    const float* w1s = (const float*)d_in[1];
    const float* W1  = (const float*)d_in[2];  // [100, 784]
    const float* b1  = (const float*)d_in[3];
    const float* w2s = (const float*)d_in[4];
    const float* W2  = (const float*)d_in[5];  // [10, 100]
    const float* b2  = (const float*)d_in[6];
    float* out = (float*)d_out;                // [1024, 10]

    prep_a_kernel<<<(NKS * 7 * 32 + 255) / 256, 256>>>(W1);
    gemm1_mma_kernel<<<dim3(M_TOT / 128, 2), 256>>>(x);
    snn_fused_kernel<<<B_BATCH, 128>>>(w1s, b1, w2s, W2, b2, out);
}